// round 13
// baseline (speedup 1.0000x reference)
#include <cuda_runtime.h>
#include <cuda_bf16.h>
#include <cstdint>

#define TT 512
#define HH 1024
#define KDIM 2048
#define NCOL 16
#define THREADS 512
#define NCTA 128

// smem byte offsets
#define W_STRIDE 4112            // 2048 bf16 + 16B pad per n-row
#define WH_OFF 0                 // 16 * 4112 = 65792
#define WL_OFF 65792
#define A_OFF  131584            // 3 bufs x (16 warps x 2KB) = 98304 B, warp-private tiles
#define STAGE_OFF A_OFF          // 8 planes x 128 x 20 floats = 81920 B (overlaid on A)
#define SMEM_BYTES 229888

__device__ __nv_bfloat16 g_xs[(size_t)128 * TT * 1024];   // x split planes: b<64 hi, b+64 lo
__device__ __nv_bfloat16 g_h0s[2][128 * 1024];
__device__ __nv_bfloat16 g_h1s[2][128 * 1024];
__device__ int g_cnt[TT + 2];

// ---------------------------------------------------------------------------
__device__ __forceinline__ uint32_t smem_u32(const void* p) {
    uint32_t a;
    asm("{ .reg .u64 t; cvta.to.shared.u64 t, %1; cvt.u32.u64 %0, t; }" : "=r"(a) : "l"(p));
    return a;
}
__device__ __forceinline__ void cp16(uint32_t d, const void* s) {
    asm volatile("cp.async.cg.shared.global [%0], [%1], 16;" :: "r"(d), "l"(s));
}
__device__ __forceinline__ void cp_commit() { asm volatile("cp.async.commit_group;"); }
template <int N>
__device__ __forceinline__ void cp_wait() { asm volatile("cp.async.wait_group %0;" :: "n"(N)); }

__device__ __forceinline__ void ldsm4(uint32_t* r, uint32_t addr) {
    asm volatile("ldmatrix.sync.aligned.m8n8.x4.shared.b16 {%0,%1,%2,%3}, [%4];"
        : "=r"(r[0]), "=r"(r[1]), "=r"(r[2]), "=r"(r[3]) : "r"(addr));
}
__device__ __forceinline__ void mma16816(float* c, const uint32_t* a, uint32_t b0, uint32_t b1) {
    asm volatile("mma.sync.aligned.m16n8k16.row.col.f32.bf16.bf16.f32 "
        "{%0,%1,%2,%3}, {%4,%5,%6,%7}, {%8,%9}, {%0,%1,%2,%3};"
        : "+f"(c[0]), "+f"(c[1]), "+f"(c[2]), "+f"(c[3])
        : "r"(a[0]), "r"(a[1]), "r"(a[2]), "r"(a[3]), "r"(b0), "r"(b1));
}

// ---------------------------------------------------------------------------
// Single prep kernel: zero states/counters + split x into bf16 hi/lo planes.
__global__ void prep_all(const float* __restrict__ x) {
    size_t i = (size_t)blockIdx.x * blockDim.x + threadIdx.x;
    size_t st = (size_t)gridDim.x * blockDim.x;
    __nv_bfloat16 z = __float2bfloat16(0.f);
    for (size_t k = i; k < 2 * 128 * 1024; k += st) { g_h0s[0][k] = z; g_h1s[0][k] = z; }
    for (size_t k = i; k < TT + 2; k += st) g_cnt[k] = 0;
    const size_t N = (size_t)64 * TT * 1024;
    for (size_t k = i; k < N; k += st) {
        float v = x[k];
        __nv_bfloat16 hi = __float2bfloat16(v);
        __nv_bfloat16 lo = __float2bfloat16(v - __bfloat162float(hi));
        size_t b = k >> 19, rest = k & ((1u << 19) - 1);   // T*H = 2^19
        g_xs[b * (size_t)(TT * 1024) + rest] = hi;
        g_xs[(b + 64) * (size_t)(TT * 1024) + rest] = lo;
    }
}

// ---------------------------------------------------------------------------
__global__ void __launch_bounds__(THREADS, 1)
rnn_mma_kernel(const float* __restrict__ W0, const float* __restrict__ b0,
               const float* __restrict__ W1, const float* __restrict__ b1,
               float* __restrict__ out) {
    extern __shared__ char smem[];
    const uint32_t sb = smem_u32(smem);
    float* stage = (float*)(smem + STAGE_OFF);   // 8 planes x 128 rows x 20 floats
    const int tid = threadIdx.x, w = tid >> 5, lane = tid & 31;
    const int mg = w & 1, kq = w >> 1;           // m-group 0..1, k-eighth 0..7
    const int cta = blockIdx.x, layer = cta >> 6, jcta = (cta & 63) * NCOL;
    const float* Wg   = layer ? W1 : W0;
    const float* bias = layer ? b1 : b0;

    // one-time: split W into SMEM, layout [n][k] bf16, row stride 4112B
    for (int i = tid; i < KDIM * NCOL; i += THREADS) {
        int k = i >> 4, n = i & 15;
        float v = Wg[(size_t)k * 1024 + jcta + n];
        __nv_bfloat16 hi = __float2bfloat16(v);
        __nv_bfloat16 lo = __float2bfloat16(v - __bfloat162float(hi));
        *(__nv_bfloat16*)(smem + WH_OFF + n * W_STRIDE + k * 2) = hi;
        *(__nv_bfloat16*)(smem + WL_OFF + n * W_STRIDE + k * 2) = lo;
    }

    // per-thread epilogue constants: thread -> (batch eb, col pair en0)
    const int eb = tid >> 3, en0 = (tid & 7) * 2;
    float bv0 = bias[jcta + en0], bv1 = bias[jcta + en0 + 1];

    // warp-private A tile region: warp w, buffer b at A_OFF + b*32768 + w*2048.
    // Within a 2KB tile: fragment f (A0,A0b,A1,A1b) at f*512; within a fragment,
    // (row r 0..15, k-half h 0..1) 16B slot at h*256 + r*16 (ldmatrix phase-
    // conflict-free: 8 rows -> 8 distinct bank quads).
    const uint32_t warpab = sb + A_OFF + (uint32_t)w * 2048u;
    const uint32_t dslot = (uint32_t)(lane & 1) * 256 + (uint32_t)(lane >> 1) * 16;
    const uint32_t lslot = (uint32_t)(lane >> 4) * 256 + (uint32_t)(lane & 15) * 16;
    const int rbase = 32 * mg + (lane >> 1);            // cp source row (hi tile 0)
    const int kelt  = (2 * kq + (lane & 1)) * 8;        // cp source k element offset
    const int bn = (lane & 7) + ((lane >> 4) << 3);
    const uint32_t bh_base = sb + WH_OFF + (uint32_t)bn * W_STRIDE
                           + (uint32_t)((lane >> 3) & 1) * 16 + (uint32_t)kq * 32;

    const size_t FSOFF = (size_t)64 * TT * HH;
    __syncthreads();

    for (int p = 0; p <= TT; p++) {
        const bool active = layer ? (p >= 1) : (p < TT);
        if (active) {
            const int t = layer ? (p - 1) : p;
            const __nv_bfloat16* s0;
            const __nv_bfloat16* s1;
            size_t rst1;
            if (layer) { s0 = g_h1s[(p + 1) & 1]; s1 = g_h0s[(p + 1) & 1]; rst1 = 1024; }
            else       { s0 = g_h0s[(p + 1) & 1]; s1 = g_xs + (size_t)t * 1024; rst1 = (size_t)TT * 1024; }

            auto issue_chunk = [&](int c, int buf) {
                const int kb = c * 128;
                const __nv_bfloat16* srcb;
                size_t rst;
                if (kb < 1024) { srcb = s0 + kb; rst = 1024; }
                else           { srcb = s1 + (kb - 1024); rst = rst1; }
                const __nv_bfloat16* sp = srcb + (size_t)rbase * rst + kelt;
                const uint32_t db = warpab + (uint32_t)buf * 32768u + dslot;
                cp16(db,        sp);                // frag A0  (hi rows +0)
                cp16(db + 512,  sp + 16 * rst);     // frag A0b (hi rows +16)
                cp16(db + 1024, sp + 64 * rst);     // frag A1  (lo rows +64)
                cp16(db + 1536, sp + 80 * rst);     // frag A1b (lo rows +80)
                cp_commit();
            };

            float ah[2][2][4], al[2][2][4];
#pragma unroll
            for (int i = 0; i < 16; i++) { (&ah[0][0][0])[i] = 0.f; (&al[0][0][0])[i] = 0.f; }

            // prologue: warp-private prefetch of chunks 0,1
            issue_chunk(0, 0);
            issue_chunk(1, 1);

#pragma unroll
            for (int c = 0; c < 16; c++) {
                __syncwarp();      // WAR: prior chunk's ldsm reads before rewriting that buffer
                if (c + 2 < 16) issue_chunk(c + 2, (c + 2) % 3);
                if (c < 14) cp_wait<2>(); else if (c < 15) cp_wait<1>(); else cp_wait<0>();
                __syncwarp();      // RAW: all lanes' staged data visible to the warp

                {
                    const uint32_t ab = warpab + (uint32_t)(c % 3) * 32768u + lslot;
                    uint32_t A0[4], A0b[4], A1[4], A1b[4], BH[4], BL[4];
                    ldsm4(A0,  ab);
                    ldsm4(A0b, ab + 512);
                    ldsm4(A1,  ab + 1024);
                    ldsm4(A1b, ab + 1536);
                    const uint32_t bo = bh_base + (uint32_t)c * 256;
                    ldsm4(BH, bo);
                    ldsm4(BL, bo + (WL_OFF - WH_OFF));
                    mma16816(ah[0][0], A0,  BH[0], BH[1]);   // ah*wh
                    mma16816(ah[0][1], A0,  BH[2], BH[3]);
                    mma16816(ah[1][0], A0b, BH[0], BH[1]);
                    mma16816(ah[1][1], A0b, BH[2], BH[3]);
                    mma16816(al[0][0], A1,  BH[0], BH[1]);   // al*wh
                    mma16816(al[0][1], A1,  BH[2], BH[3]);
                    mma16816(al[1][0], A1b, BH[0], BH[1]);
                    mma16816(al[1][1], A1b, BH[2], BH[3]);
                    mma16816(ah[0][0], A0,  BL[0], BL[1]);   // ah*wl (same acc)
                    mma16816(ah[0][1], A0,  BL[2], BL[3]);
                    mma16816(ah[1][0], A0b, BL[0], BL[1]);
                    mma16816(ah[1][1], A0b, BL[2], BL[3]);
                }
            }
            __syncthreads();   // all warps done with A buffers -> stage overlay safe

            // write C fragments to stage plane kq
            {
                const int r0 = 32 * mg + (lane >> 2);
                const int cc = 2 * (lane & 3);
                float* stg = stage + kq * (128 * 20);
#pragma unroll
                for (int tt2 = 0; tt2 < 2; tt2++) {
                    const int rbs = r0 + 16 * tt2;
#pragma unroll
                    for (int nt = 0; nt < 2; nt++) {
                        const int col = 8 * nt + cc;
                        stg[rbs * 20 + col]            = ah[tt2][nt][0];
                        stg[rbs * 20 + col + 1]        = ah[tt2][nt][1];
                        stg[(rbs + 8) * 20 + col]      = ah[tt2][nt][2];
                        stg[(rbs + 8) * 20 + col + 1]  = ah[tt2][nt][3];
                        stg[(64 + rbs) * 20 + col]     = al[tt2][nt][0];
                        stg[(64 + rbs) * 20 + col + 1] = al[tt2][nt][1];
                        stg[(72 + rbs) * 20 + col]     = al[tt2][nt][2];
                        stg[(72 + rbs) * 20 + col + 1] = al[tt2][nt][3];
                    }
                }
            }
            __syncthreads();

            // combine 8 k-planes and hi/lo rows, bias, tanh, split-store h
            {
                float s0v = bv0, s1v = bv1;
#pragma unroll
                for (int q = 0; q < 8; q++) {
                    const float* st0 = stage + q * (128 * 20) + eb * 20 + en0;
                    s0v += st0[0] + st0[64 * 20];
                    s1v += st0[1] + st0[64 * 20 + 1];
                }
                float h0f = tanhf(s0v), h1f = tanhf(s1v);

                __nv_bfloat16 h0 = __float2bfloat16(h0f);
                __nv_bfloat16 h1 = __float2bfloat16(h1f);
                __nv_bfloat16 l0 = __float2bfloat16(h0f - __bfloat162float(h0));
                __nv_bfloat16 l1 = __float2bfloat16(h1f - __bfloat162float(h1));
                uint32_t hw = (uint32_t)*(uint16_t*)&h0 | ((uint32_t)*(uint16_t*)&h1 << 16);
                uint32_t lw = (uint32_t)*(uint16_t*)&l0 | ((uint32_t)*(uint16_t*)&l1 << 16);

                __nv_bfloat16* hp = layer ? g_h1s[p & 1] : g_h0s[p & 1];
                __stcg((uint32_t*)(hp + (size_t)eb * 1024 + jcta + en0), hw);
                __stcg((uint32_t*)(hp + (size_t)(eb + 64) * 1024 + jcta + en0), lw);

                float2 of = make_float2(h0f, h1f);
                if (layer) {
                    *(float2*)(out + ((size_t)eb * TT + t) * HH + jcta + en0) = of;
                    if (t == TT - 1)
                        *(float2*)(out + FSOFF + (size_t)eb * 2048 + 1024 + jcta + en0) = of;
                } else if (p == TT - 1) {
                    *(float2*)(out + FSOFF + (size_t)eb * 2048 + jcta + en0) = of;
                }
            }
        }

        // ---- grid barrier: per-phase counter (verbatim R9/R12, proven) ----
        __threadfence();
        __syncthreads();
        if (tid == 0) {
            atomicAdd(&g_cnt[p], 1);
            volatile int* cp = (volatile int*)&g_cnt[p];
            while (*cp < NCTA) { __nanosleep(32); }
        }
        __syncthreads();
    }
}

// ---------------------------------------------------------------------------
extern "C" void kernel_launch(void* const* d_in, const int* in_sizes, int n_in,
                              void* d_out, int out_size) {
    const float* x  = (const float*)d_in[0];
    const float* W0 = (const float*)d_in[1];
    const float* b0 = (const float*)d_in[2];
    const float* W1 = (const float*)d_in[3];
    const float* b1 = (const float*)d_in[4];
    float* out = (float*)d_out;

    cudaFuncSetAttribute(rnn_mma_kernel,
                         cudaFuncAttributeMaxDynamicSharedMemorySize, SMEM_BYTES);
    prep_all<<<512, 256>>>(x);
    rnn_mma_kernel<<<NCTA, THREADS, SMEM_BYTES>>>(W0, b0, W1, b1, out);
}

// round 15
// speedup vs baseline: 2.3293x; 2.3293x over previous
#include <cuda_runtime.h>
#include <cuda_bf16.h>
#include <cstdint>

#define TT 512
#define HH 1024
#define KDIM 2048
#define NCOL 16
#define THREADS 512
#define NCTA 128

// smem byte offsets
#define W_STRIDE 4112            // 2048 bf16 + 16B pad per n-row
#define WH_OFF 0                 // 16 * 4112 = 65792
#define WL_OFF 65792
#define A_OFF  131584            // 2 groups x 3 bufs x 16384 B (64 rows x 256 B, XOR-swizzled)
#define A_GRP  49152             // per-group region (3 buffers)
#define A_BUFG 16384             // per-group per-buffer
#define STAGE_OFF A_OFF          // 8 planes x 128 x 20 floats = 81920 B (overlaid on A)
#define SMEM_BYTES 229888

__device__ __nv_bfloat16 g_xs[(size_t)128 * TT * 1024];   // x split planes: b<64 hi, b+64 lo
__device__ __nv_bfloat16 g_h0s[2][128 * 1024];
__device__ __nv_bfloat16 g_h1s[2][128 * 1024];
__device__ int g_cnt[TT + 2];

// ---------------------------------------------------------------------------
__device__ __forceinline__ uint32_t smem_u32(const void* p) {
    uint32_t a;
    asm("{ .reg .u64 t; cvta.to.shared.u64 t, %1; cvt.u32.u64 %0, t; }" : "=r"(a) : "l"(p));
    return a;
}
__device__ __forceinline__ void cp16(uint32_t d, const void* s) {
    asm volatile("cp.async.cg.shared.global [%0], [%1], 16;" :: "r"(d), "l"(s));
}
__device__ __forceinline__ void cp_commit() { asm volatile("cp.async.commit_group;"); }
template <int N>
__device__ __forceinline__ void cp_wait() { asm volatile("cp.async.wait_group %0;" :: "n"(N)); }

// Named barrier over one m-group (8 warps = 256 threads). bar.sync includes
// CTA-scope memory ordering among participants (same guarantee pattern as the
// classic cp.async + __syncthreads handoff, restricted to the group).
__device__ __forceinline__ void bar_grp(int id) {
    asm volatile("bar.sync %0, 256;" :: "r"(id) : "memory");
}

__device__ __forceinline__ void ldsm4(uint32_t* r, uint32_t addr) {
    asm volatile("ldmatrix.sync.aligned.m8n8.x4.shared.b16 {%0,%1,%2,%3}, [%4];"
        : "=r"(r[0]), "=r"(r[1]), "=r"(r[2]), "=r"(r[3]) : "r"(addr));
}
__device__ __forceinline__ void mma16816(float* c, const uint32_t* a, uint32_t b0, uint32_t b1) {
    asm volatile("mma.sync.aligned.m16n8k16.row.col.f32.bf16.bf16.f32 "
        "{%0,%1,%2,%3}, {%4,%5,%6,%7}, {%8,%9}, {%0,%1,%2,%3};"
        : "+f"(c[0]), "+f"(c[1]), "+f"(c[2]), "+f"(c[3])
        : "r"(a[0]), "r"(a[1]), "r"(a[2]), "r"(a[3]), "r"(b0), "r"(b1));
}

// ---------------------------------------------------------------------------
// Single prep kernel: zero states/counters + split x into bf16 hi/lo planes.
__global__ void prep_all(const float* __restrict__ x) {
    size_t i = (size_t)blockIdx.x * blockDim.x + threadIdx.x;
    size_t st = (size_t)gridDim.x * blockDim.x;
    __nv_bfloat16 z = __float2bfloat16(0.f);
    for (size_t k = i; k < 2 * 128 * 1024; k += st) { g_h0s[0][k] = z; g_h1s[0][k] = z; }
    for (size_t k = i; k < TT + 2; k += st) g_cnt[k] = 0;
    const size_t N = (size_t)64 * TT * 1024;
    for (size_t k = i; k < N; k += st) {
        float v = x[k];
        __nv_bfloat16 hi = __float2bfloat16(v);
        __nv_bfloat16 lo = __float2bfloat16(v - __bfloat162float(hi));
        size_t b = k >> 19, rest = k & ((1u << 19) - 1);   // T*H = 2^19
        g_xs[b * (size_t)(TT * 1024) + rest] = hi;
        g_xs[(b + 64) * (size_t)(TT * 1024) + rest] = lo;
    }
}

// ---------------------------------------------------------------------------
__global__ void __launch_bounds__(THREADS, 1)
rnn_mma_kernel(const float* __restrict__ W0, const float* __restrict__ b0,
               const float* __restrict__ W1, const float* __restrict__ b1,
               float* __restrict__ out) {
    extern __shared__ char smem[];
    const uint32_t sb = smem_u32(smem);
    float* stage = (float*)(smem + STAGE_OFF);   // 8 planes x 128 rows x 20 floats
    const int tid = threadIdx.x, w = tid >> 5, lane = tid & 31;
    const int mg = w & 1, kq = w >> 1;           // m-group 0..1, k-eighth 0..7
    const int cta = blockIdx.x, layer = cta >> 6, jcta = (cta & 63) * NCOL;
    const float* Wg   = layer ? W1 : W0;
    const float* bias = layer ? b1 : b0;

    // one-time: split W into SMEM, layout [n][k] bf16, row stride 4112B
    for (int i = tid; i < KDIM * NCOL; i += THREADS) {
        int k = i >> 4, n = i & 15;
        float v = Wg[(size_t)k * 1024 + jcta + n];
        __nv_bfloat16 hi = __float2bfloat16(v);
        __nv_bfloat16 lo = __float2bfloat16(v - __bfloat162float(hi));
        *(__nv_bfloat16*)(smem + WH_OFF + n * W_STRIDE + k * 2) = hi;
        *(__nv_bfloat16*)(smem + WL_OFF + n * W_STRIDE + k * 2) = lo;
    }

    // per-thread epilogue constants: thread -> (batch eb, col pair en0)
    const int eb = tid >> 3, en0 = (tid & 7) * 2;
    float bv0 = bias[jcta + en0], bv1 = bias[jcta + en0 + 1];

    // Group-private A region: group mg holds ITS 64 rows per chunk:
    //   group-row gr 0..31  = global hi rows 32mg + gr
    //   group-row gr 32..63 = global lo rows 64 + 32mg + (gr-32)
    // Row layout: 256B per group-row, XOR swizzle (chunk16B ^ (gr&7)).
    const uint32_t gbase = sb + A_OFF + (uint32_t)mg * A_GRP;

    // ldsm fragment addressing (consumers read only their own group's rows)
    const int c0log = 2 * kq + (lane >> 4);      // logical 16B-chunk (0..15)
    const uint32_t ax = (uint32_t)((c0log ^ (lane & 7)) << 4);
    const uint32_t lrow = (uint32_t)(lane & 15) << 8;   // group-rows 0..15
    const int bn = (lane & 7) + ((lane >> 4) << 3);
    const uint32_t bh_base = sb + WH_OFF + (uint32_t)bn * W_STRIDE
                           + (uint32_t)((lane >> 3) & 1) * 16 + (uint32_t)kq * 32;

    // cp.async mapping within group: gtid 0..255 -> (seg = gtid&15, rb = gtid>>4)
    // rows gr = rb + 16j (j=0..3); 16 threads cover each 256B row (coalesced).
    const int gtid = (w >> 1) * 32 + lane;
    const int seg = gtid & 15, rb = gtid >> 4;   // rb 0..15
    const uint32_t dstb = gbase + ((uint32_t)rb << 8) + (uint32_t)((seg ^ (rb & 7)) << 4);

    const size_t FSOFF = (size_t)64 * TT * HH;
    __syncthreads();

    for (int p = 0; p <= TT; p++) {
        const bool active = layer ? (p >= 1) : (p < TT);
        if (active) {
            const int t = layer ? (p - 1) : p;
            const __nv_bfloat16* s0;
            const __nv_bfloat16* s1;
            size_t rst1;
            if (layer) { s0 = g_h1s[(p + 1) & 1]; s1 = g_h0s[(p + 1) & 1]; rst1 = 1024; }
            else       { s0 = g_h0s[(p + 1) & 1]; s1 = g_xs + (size_t)t * 1024; rst1 = (size_t)TT * 1024; }

            // stage group's 64 rows of one 128-k chunk into buffer buf
            auto issue_chunk = [&](int c, int buf) {
                const int kb = c * 128;
                const __nv_bfloat16* srcb;
                size_t rst;
                if (kb < 1024) { srcb = s0 + kb; rst = 1024; }
                else           { srcb = s1 + (kb - 1024); rst = rst1; }
                // j=0 source row: hi row 32mg + rb; j deltas: +16, +64, +80
                const __nv_bfloat16* sp = srcb + (size_t)(32 * mg + rb) * rst + seg * 8;
                const uint32_t db = dstb + (uint32_t)buf * A_BUFG;
                cp16(db,             sp);
                cp16(db + 16 * 256,  sp + 16 * rst);
                cp16(db + 32 * 256,  sp + 64 * rst);
                cp16(db + 48 * 256,  sp + 80 * rst);
                cp_commit();
            };

            float ah[2][2][4], al[2][2][4];
#pragma unroll
            for (int i = 0; i < 16; i++) { (&ah[0][0][0])[i] = 0.f; (&al[0][0][0])[i] = 0.f; }

            // prologue: group-cooperative prefetch of chunks 0,1
            issue_chunk(0, 0);
            issue_chunk(1, 1);

            for (int c = 0; c < 16; c++) {
                if (c < 15) cp_wait<1>(); else cp_wait<0>();
                bar_grp(1 + mg);   // group: chunk c visible + chunk c-1 consumers done

                if (c + 2 < 16) issue_chunk(c + 2, (c + 2) % 3);

                {
                    const uint32_t ab = gbase + (uint32_t)(c % 3) * A_BUFG + lrow + ax;
                    uint32_t A0[4], A0b[4], A1[4], A1b[4], BH[4], BL[4];
                    ldsm4(A0,  ab);                 // hi tile 0 (group-rows 0..15)
                    ldsm4(A0b, ab + 4096);          // hi tile 1 (group-rows 16..31)
                    ldsm4(A1,  ab + 8192);          // lo tile 0 (group-rows 32..47)
                    ldsm4(A1b, ab + 12288);         // lo tile 1 (group-rows 48..63)
                    const uint32_t bo = bh_base + (uint32_t)c * 256;
                    ldsm4(BH, bo);
                    ldsm4(BL, bo + (WL_OFF - WH_OFF));
                    mma16816(ah[0][0], A0,  BH[0], BH[1]);   // ah*wh
                    mma16816(ah[0][1], A0,  BH[2], BH[3]);
                    mma16816(ah[1][0], A0b, BH[0], BH[1]);
                    mma16816(ah[1][1], A0b, BH[2], BH[3]);
                    mma16816(al[0][0], A1,  BH[0], BH[1]);   // al*wh
                    mma16816(al[0][1], A1,  BH[2], BH[3]);
                    mma16816(al[1][0], A1b, BH[0], BH[1]);
                    mma16816(al[1][1], A1b, BH[2], BH[3]);
                    mma16816(ah[0][0], A0,  BL[0], BL[1]);   // ah*wl (same acc)
                    mma16816(ah[0][1], A0,  BL[2], BL[3]);
                    mma16816(ah[1][0], A0b, BL[0], BL[1]);
                    mma16816(ah[1][1], A0b, BL[2], BL[3]);
                }
            }
            __syncthreads();   // both groups done with A buffers -> stage overlay safe

            // write C fragments to stage plane kq
            {
                const int r0 = 32 * mg + (lane >> 2);
                const int cc = 2 * (lane & 3);
                float* stg = stage + kq * (128 * 20);
#pragma unroll
                for (int tt2 = 0; tt2 < 2; tt2++) {
                    const int rbs = r0 + 16 * tt2;
#pragma unroll
                    for (int nt = 0; nt < 2; nt++) {
                        const int col = 8 * nt + cc;
                        stg[rbs * 20 + col]            = ah[tt2][nt][0];
                        stg[rbs * 20 + col + 1]        = ah[tt2][nt][1];
                        stg[(rbs + 8) * 20 + col]      = ah[tt2][nt][2];
                        stg[(rbs + 8) * 20 + col + 1]  = ah[tt2][nt][3];
                        stg[(64 + rbs) * 20 + col]     = al[tt2][nt][0];
                        stg[(64 + rbs) * 20 + col + 1] = al[tt2][nt][1];
                        stg[(72 + rbs) * 20 + col]     = al[tt2][nt][2];
                        stg[(72 + rbs) * 20 + col + 1] = al[tt2][nt][3];
                    }
                }
            }
            __syncthreads();

            // combine 8 k-planes and hi/lo rows, bias, tanh, split-store h
            {
                float s0v = bv0, s1v = bv1;
#pragma unroll
                for (int q = 0; q < 8; q++) {
                    const float* st0 = stage + q * (128 * 20) + eb * 20 + en0;
                    s0v += st0[0] + st0[64 * 20];
                    s1v += st0[1] + st0[64 * 20 + 1];
                }
                float h0f = tanhf(s0v), h1f = tanhf(s1v);

                __nv_bfloat16 h0 = __float2bfloat16(h0f);
                __nv_bfloat16 h1 = __float2bfloat16(h1f);
                __nv_bfloat16 l0 = __float2bfloat16(h0f - __bfloat162float(h0));
                __nv_bfloat16 l1 = __float2bfloat16(h1f - __bfloat162float(h1));
                uint32_t hw = (uint32_t)*(uint16_t*)&h0 | ((uint32_t)*(uint16_t*)&h1 << 16);
                uint32_t lw = (uint32_t)*(uint16_t*)&l0 | ((uint32_t)*(uint16_t*)&l1 << 16);

                __nv_bfloat16* hp = layer ? g_h1s[p & 1] : g_h0s[p & 1];
                __stcg((uint32_t*)(hp + (size_t)eb * 1024 + jcta + en0), hw);
                __stcg((uint32_t*)(hp + (size_t)(eb + 64) * 1024 + jcta + en0), lw);

                float2 of = make_float2(h0f, h1f);
                if (layer) {
                    *(float2*)(out + ((size_t)eb * TT + t) * HH + jcta + en0) = of;
                    if (t == TT - 1)
                        *(float2*)(out + FSOFF + (size_t)eb * 2048 + 1024 + jcta + en0) = of;
                } else if (p == TT - 1) {
                    *(float2*)(out + FSOFF + (size_t)eb * 2048 + jcta + en0) = of;
                }
            }
        }

        // ---- grid barrier: per-phase counter (verbatim R9/R12, proven) ----
        __threadfence();
        __syncthreads();
        if (tid == 0) {
            atomicAdd(&g_cnt[p], 1);
            volatile int* cp = (volatile int*)&g_cnt[p];
            while (*cp < NCTA) { __nanosleep(32); }
        }
        __syncthreads();
    }
}

// ---------------------------------------------------------------------------
extern "C" void kernel_launch(void* const* d_in, const int* in_sizes, int n_in,
                              void* d_out, int out_size) {
    const float* x  = (const float*)d_in[0];
    const float* W0 = (const float*)d_in[1];
    const float* b0 = (const float*)d_in[2];
    const float* W1 = (const float*)d_in[3];
    const float* b1 = (const float*)d_in[4];
    float* out = (float*)d_out;

    cudaFuncSetAttribute(rnn_mma_kernel,
                         cudaFuncAttributeMaxDynamicSharedMemorySize, SMEM_BYTES);
    prep_all<<<512, 256>>>(x);
    rnn_mma_kernel<<<NCTA, THREADS, SMEM_BYTES>>>(W0, b0, W1, b1, out);
}